// round 14
// baseline (speedup 1.0000x reference)
#include <cuda_runtime.h>

#define Bn 32
#define Sn 2048
#define Dn 1024
#define K1S 32          // S-splits in K1 / chunks in K3 (64 rows each)
#define RPS 64          // rows per split/chunk

// ---- scratch (device globals; no allocations allowed) ----
__device__ float g_ysp[K1S * Bn * Dn];   // [split][b][d] partial column sums (4 MB)
__device__ float g_ys[Bn * Dn];          // column sums of E over S
__device__ float g_u[Bn * Dn];           // u[b,d] = sum_e W[d,e]*ys_sum[b,e]
__device__ float g_acc[Bn * K1S * Dn];   // per-(b,chunk) partial zs (4 MB)
__device__ float g_m[Bn * K1S];          // per-(b,chunk) softmax max
__device__ float g_Z[Bn * K1S];          // per-(b,chunk) softmax denom (at g_m)
__device__ int   g_mode;                 // mask dtype: 0=u8 1=i32 2=f32

// ===================== K1: partial column sums of E =====================
// grid 1024 = (b:32) x (split:32); 256 threads, thread t owns float4 col t.
// Lean: 4 accumulators, ~40 regs -> high occupancy streaming.
__global__ __launch_bounds__(256) void k1_colsum(const float* __restrict__ E,
                                                 const unsigned int* __restrict__ maskw) {
    int bx = blockIdx.x;
    int b  = bx >> 5;
    int sh = bx & 31;
    int t  = threadIdx.x;

    if (bx == 0 && t == 0) {
        bool allLe1 = true, allF = true;
        #pragma unroll 4
        for (int i = 0; i < 64; i++) {
            unsigned int v = maskw[i];
            if (v > 1u) allLe1 = false;
            if (v != 0u && v != 0x3F800000u) allF = false;
        }
        g_mode = allLe1 ? 1 : (allF ? 2 : 0);
    }

    const float4* p = reinterpret_cast<const float4*>(E)
                    + (size_t)(b * Sn + sh * RPS) * 256 + t;
    float4 a0 = make_float4(0.f,0.f,0.f,0.f), a1 = a0, a2 = a0, a3 = a0;
    #pragma unroll 4
    for (int s = 0; s < RPS; s += 4) {
        float4 v0 = p[(size_t)(s + 0) * 256];
        float4 v1 = p[(size_t)(s + 1) * 256];
        float4 v2 = p[(size_t)(s + 2) * 256];
        float4 v3 = p[(size_t)(s + 3) * 256];
        a0.x += v0.x; a0.y += v0.y; a0.z += v0.z; a0.w += v0.w;
        a1.x += v1.x; a1.y += v1.y; a1.z += v1.z; a1.w += v1.w;
        a2.x += v2.x; a2.y += v2.y; a2.z += v2.z; a2.w += v2.w;
        a3.x += v3.x; a3.y += v3.y; a3.z += v3.z; a3.w += v3.w;
    }
    float4 s4 = make_float4((a0.x + a1.x) + (a2.x + a3.x),
                            (a0.y + a1.y) + (a2.y + a3.y),
                            (a0.z + a1.z) + (a2.z + a3.z),
                            (a0.w + a1.w) + (a2.w + a3.w));
    reinterpret_cast<float4*>(g_ysp)[(size_t)(sh * Bn + b) * 256 + t] = s4;
}

// ===================== K1r: reduce 32 slices -> g_ys; zero g_u ==============
__global__ __launch_bounds__(256) void k1_reduce() {
    int b = blockIdx.x, t = threadIdx.x;
    const float4* base = reinterpret_cast<const float4*>(g_ysp);
    float4 s = make_float4(0.f, 0.f, 0.f, 0.f);
    #pragma unroll
    for (int c = 0; c < K1S; c++) {
        float4 v = base[(size_t)(c * Bn + b) * 256 + t];
        s.x += v.x; s.y += v.y; s.z += v.z; s.w += v.w;
    }
    reinterpret_cast<float4*>(g_ys)[b * 256 + t] = s;
    reinterpret_cast<float4*>(g_u)[b * 256 + t] = make_float4(0.f, 0.f, 0.f, 0.f);
}

// ===================== K2: u[b,d] = sum_e W[d,e] * ys_sum[b,e] =====================
__global__ __launch_bounds__(256) void k2_u(const float* __restrict__ W) {
    __shared__ float Ws[64 * 65];   // padded rows: conflict-free column reads
    __shared__ float Ys[32 * 64];
    int dt = blockIdx.x >> 4, es = blockIdx.x & 15;
    int d0 = dt * 64, e0 = es * 64;
    int t = threadIdx.x;
    #pragma unroll
    for (int k = 0; k < 16; k++) {
        int idx = t + k * 256;
        int r = idx >> 6, c = idx & 63;
        Ws[r * 65 + c] = W[(size_t)(d0 + r) * Dn + e0 + c];
    }
    #pragma unroll
    for (int k = 0; k < 8; k++) {
        int idx = t + k * 256;
        int b = idx >> 6, c = idx & 63;
        Ys[b * 64 + c] = g_ys[b * Dn + e0 + c];
    }
    __syncthreads();
    int bg = t >> 5, dg = t & 31;
    float a00=0,a01=0,a10=0,a11=0,a20=0,a21=0,a30=0,a31=0;
    #pragma unroll 8
    for (int c = 0; c < 64; c++) {
        float w0 = Ws[dg * 65 + c];
        float w1 = Ws[(dg + 32) * 65 + c];
        float y0 = Ys[(bg * 4 + 0) * 64 + c];
        float y1 = Ys[(bg * 4 + 1) * 64 + c];
        float y2 = Ys[(bg * 4 + 2) * 64 + c];
        float y3 = Ys[(bg * 4 + 3) * 64 + c];
        a00 += y0 * w0; a01 += y0 * w1;
        a10 += y1 * w0; a11 += y1 * w1;
        a20 += y2 * w0; a21 += y2 * w1;
        a30 += y3 * w0; a31 += y3 * w1;
    }
    atomicAdd(&g_u[(bg * 4 + 0) * Dn + d0 + dg],      a00);
    atomicAdd(&g_u[(bg * 4 + 0) * Dn + d0 + dg + 32], a01);
    atomicAdd(&g_u[(bg * 4 + 1) * Dn + d0 + dg],      a10);
    atomicAdd(&g_u[(bg * 4 + 1) * Dn + d0 + dg + 32], a11);
    atomicAdd(&g_u[(bg * 4 + 2) * Dn + d0 + dg],      a20);
    atomicAdd(&g_u[(bg * 4 + 2) * Dn + d0 + dg + 32], a21);
    atomicAdd(&g_u[(bg * 4 + 3) * Dn + d0 + dg],      a30);
    atomicAdd(&g_u[(bg * 4 + 3) * Dn + d0 + dg + 32], a31);
}

// ===================== K3: fused f + online softmax + partial zs ====================
// ROW-PARALLEL: block covers all 1024 cols of each row; warp w owns cols
// [128w,128w+128), lane owns one float4. Per-thread state: u(4)+acc(4)+r(16)
// regs -> no spill, 4-5 CTAs/SM. Rows processed in batches of 4.
__global__ __launch_bounds__(256, 4) void k3_main(
    const float* __restrict__ E, const void* __restrict__ maskp,
    float* __restrict__ fout)
{
    __shared__ float sPart[4][8];   // [row-in-batch][warp] partial dots
    __shared__ float sF[4];         // broadcast logits

    int t = threadIdx.x, w = t >> 5, lane = t & 31;
    int bx = blockIdx.x;
    int b = bx >> 5, chunk = bx & 31;
    int mode = g_mode;

    // thread-resident u slice (its own 4 columns), scaled by 1/S (folds mean)
    float4 u;
    {
        const float invS = 1.0f / 2048.0f;
        u = reinterpret_cast<const float4*>(g_u + b * Dn)[t];
        u.x *= invS; u.y *= invS; u.z *= invS; u.w *= invS;
    }

    float4 acc = make_float4(0.f, 0.f, 0.f, 0.f);
    float m = -1.0e30f, Z = 0.f;

    int s0 = chunk * RPS;
    const float4* Ebase = reinterpret_cast<const float4*>(E)
                        + (size_t)(b * Sn + s0) * 256 + t;   // t == w*32+lane

    #pragma unroll 1
    for (int batch = 0; batch < RPS / 4; batch++) {
        // front-batched loads: 4 rows, this thread's float4 column
        float4 r0 = Ebase[(size_t)(batch * 4 + 0) * 256];
        float4 r1 = Ebase[(size_t)(batch * 4 + 1) * 256];
        float4 r2 = Ebase[(size_t)(batch * 4 + 2) * 256];
        float4 r3 = Ebase[(size_t)(batch * 4 + 3) * 256];

        // warp-partial dots over this warp's 128 columns
        float d0 = r0.x*u.x + r0.y*u.y + r0.z*u.z + r0.w*u.w;
        float d1 = r1.x*u.x + r1.y*u.y + r1.z*u.z + r1.w*u.w;
        float d2 = r2.x*u.x + r2.y*u.y + r2.z*u.z + r2.w*u.w;
        float d3 = r3.x*u.x + r3.y*u.y + r3.z*u.z + r3.w*u.w;
        #pragma unroll
        for (int o = 16; o; o >>= 1) {
            d0 += __shfl_xor_sync(0xffffffffu, d0, o);
            d1 += __shfl_xor_sync(0xffffffffu, d1, o);
            d2 += __shfl_xor_sync(0xffffffffu, d2, o);
            d3 += __shfl_xor_sync(0xffffffffu, d3, o);
        }
        if (lane == 0) {
            sPart[0][w] = d0; sPart[1][w] = d1;
            sPart[2][w] = d2; sPart[3][w] = d3;
        }
        __syncthreads();

        // warp 0 finishes the 4 rows: lane groups of 8 reduce one row each
        if (w == 0) {
            int i = lane >> 3, j = lane & 7;
            float v = sPart[i][j];
            v += __shfl_xor_sync(0xffffffffu, v, 4);
            v += __shfl_xor_sync(0xffffffffu, v, 2);
            v += __shfl_xor_sync(0xffffffffu, v, 1);
            if (j == 0) {
                int s = s0 + batch * 4 + i;
                int midx = b * Sn + s;
                bool mk;
                if (mode == 1)      mk = ((const int*)maskp)[midx] != 0;
                else if (mode == 2) mk = ((const float*)maskp)[midx] != 0.f;
                else                mk = ((const unsigned char*)maskp)[midx] != 0;
                float f = mk ? v : -1.0e9f;
                fout[midx] = f;          // raw logit; K4 normalizes
                sF[i] = f;
            }
        }
        __syncthreads();

        // all threads update block-uniform softmax state + their acc columns
        float f0 = sF[0], f1 = sF[1], f2 = sF[2], f3 = sF[3];
        float fm = fmaxf(fmaxf(f0, f1), fmaxf(f2, f3));
        if (fm > m) {                    // block-uniform branch, rare
            float sc = __expf(m - fm);
            acc.x *= sc; acc.y *= sc; acc.z *= sc; acc.w *= sc;
            Z *= sc;
            m = fm;
        }
        float p0 = __expf(f0 - m), p1 = __expf(f1 - m);
        float p2 = __expf(f2 - m), p3 = __expf(f3 - m);
        Z += (p0 + p1) + (p2 + p3);
        acc.x += p0*r0.x + p1*r1.x + p2*r2.x + p3*r3.x;
        acc.y += p0*r0.y + p1*r1.y + p2*r2.y + p3*r3.y;
        acc.z += p0*r0.z + p1*r1.z + p2*r2.z + p3*r3.z;
        acc.w += p0*r0.w + p1*r1.w + p2*r2.w + p3*r3.w;
    }

    // direct store: 256 threads tile the 1024 cols exactly once
    reinterpret_cast<float4*>(g_acc)[(size_t)bx * 256 + t] = acc;
    if (t == 0) { g_m[bx] = m; g_Z[bx] = Z; }
}

// ===================== K4: merge 32 chunks, write zs, normalize f ==================
// grid 256 = (b:32) x (part:8); 256 threads.
__global__ __launch_bounds__(256) void k4_final(float* __restrict__ out) {
    int bx = blockIdx.x;
    int b = bx >> 3, j = bx & 7;
    int t = threadIdx.x;

    float M = -1.0e30f;
    #pragma unroll
    for (int c = 0; c < K1S; c++) M = fmaxf(M, g_m[b * K1S + c]);
    float sc[K1S];
    float Z = 0.f;
    #pragma unroll
    for (int c = 0; c < K1S; c++) {
        sc[c] = __expf(g_m[b * K1S + c] - M);
        Z += g_Z[b * K1S + c] * sc[c];
    }
    float rinv = 1.0f / Z;

    if (t < 128) {
        int col = j * 128 + t;
        float s = 0.f;
        #pragma unroll
        for (int c = 0; c < K1S; c++)
            s += sc[c] * g_acc[((size_t)(b * K1S + c) << 10) + col];
        out[b * Dn + col] = s * rinv;
    }

    float* f = out + Bn * Dn;
    int idx = b * Sn + j * 256 + t;
    f[idx] = __expf(f[idx] - M) * rinv;
}

extern "C" void kernel_launch(void* const* d_in, const int* in_sizes, int n_in,
                              void* d_out, int out_size) {
    const float* E    = (const float*)d_in[0];
    const void*  mask = d_in[1];
    const float* W    = (const float*)d_in[2];
    float* out = (float*)d_out;

    k1_colsum<<<1024, 256>>>(E, (const unsigned int*)mask);
    k1_reduce<<<32, 256>>>();
    k2_u     <<<256, 256>>>(W);
    k3_main  <<<1024, 256>>>(E, mask, out + Bn * Dn);
    k4_final <<<256, 256>>>(out);
}

// round 15
// speedup vs baseline: 1.0054x; 1.0054x over previous
#include <cuda_runtime.h>

#define Bn 32
#define Sn 2048
#define Dn 1024
#define K1S 32          // S-splits in K1 / chunks in K3 (64 rows each)
#define RPS 64          // rows per split/chunk

// ---- scratch (device globals; no allocations allowed) ----
__device__ float g_ysp[K1S * Bn * Dn];   // [split][b][d] partial column sums (4 MB)
__device__ float g_ys[Bn * Dn];          // column sums of E over S
__device__ float g_u[Bn * Dn];           // u[b,d] = sum_e W[d,e]*ys_sum[b,e]
__device__ float g_acc[Bn * K1S * Dn];   // per-(b,chunk) partial zs (4 MB)
__device__ float g_m[Bn * K1S];          // per-(b,chunk) softmax max
__device__ float g_Z[Bn * K1S];          // per-(b,chunk) softmax denom (at g_m)
__device__ int   g_mode;                 // mask dtype: 0=u8 1=i32 2=f32

// ===================== K1: partial column sums of E =====================
// grid 1024 = (b:32) x (split:32); 256 threads, thread t owns float4 col t.
// Lean: 4 accumulators, ~40 regs -> high occupancy streaming.
__global__ __launch_bounds__(256) void k1_colsum(const float* __restrict__ E,
                                                 const unsigned int* __restrict__ maskw) {
    int bx = blockIdx.x;
    int b  = bx >> 5;
    int sh = bx & 31;
    int t  = threadIdx.x;

    if (bx == 0 && t == 0) {
        bool allLe1 = true, allF = true;
        #pragma unroll 4
        for (int i = 0; i < 64; i++) {
            unsigned int v = maskw[i];
            if (v > 1u) allLe1 = false;
            if (v != 0u && v != 0x3F800000u) allF = false;
        }
        g_mode = allLe1 ? 1 : (allF ? 2 : 0);
    }

    const float4* p = reinterpret_cast<const float4*>(E)
                    + (size_t)(b * Sn + sh * RPS) * 256 + t;
    float4 a0 = make_float4(0.f,0.f,0.f,0.f), a1 = a0, a2 = a0, a3 = a0;
    #pragma unroll 4
    for (int s = 0; s < RPS; s += 4) {
        float4 v0 = p[(size_t)(s + 0) * 256];
        float4 v1 = p[(size_t)(s + 1) * 256];
        float4 v2 = p[(size_t)(s + 2) * 256];
        float4 v3 = p[(size_t)(s + 3) * 256];
        a0.x += v0.x; a0.y += v0.y; a0.z += v0.z; a0.w += v0.w;
        a1.x += v1.x; a1.y += v1.y; a1.z += v1.z; a1.w += v1.w;
        a2.x += v2.x; a2.y += v2.y; a2.z += v2.z; a2.w += v2.w;
        a3.x += v3.x; a3.y += v3.y; a3.z += v3.z; a3.w += v3.w;
    }
    float4 s4 = make_float4((a0.x + a1.x) + (a2.x + a3.x),
                            (a0.y + a1.y) + (a2.y + a3.y),
                            (a0.z + a1.z) + (a2.z + a3.z),
                            (a0.w + a1.w) + (a2.w + a3.w));
    reinterpret_cast<float4*>(g_ysp)[(size_t)(sh * Bn + b) * 256 + t] = s4;
}

// ===================== K1r: reduce 32 slices -> g_ys; zero g_u ==============
__global__ __launch_bounds__(256) void k1_reduce() {
    int b = blockIdx.x, t = threadIdx.x;
    const float4* base = reinterpret_cast<const float4*>(g_ysp);
    float4 s = make_float4(0.f, 0.f, 0.f, 0.f);
    #pragma unroll
    for (int c = 0; c < K1S; c++) {
        float4 v = base[(size_t)(c * Bn + b) * 256 + t];
        s.x += v.x; s.y += v.y; s.z += v.z; s.w += v.w;
    }
    reinterpret_cast<float4*>(g_ys)[b * 256 + t] = s;
    reinterpret_cast<float4*>(g_u)[b * 256 + t] = make_float4(0.f, 0.f, 0.f, 0.f);
}

// ===================== K2: u[b,d] = sum_e W[d,e] * ys_sum[b,e] =====================
__global__ __launch_bounds__(256) void k2_u(const float* __restrict__ W) {
    __shared__ float Ws[64 * 65];   // padded rows: conflict-free column reads
    __shared__ float Ys[32 * 64];
    int dt = blockIdx.x >> 4, es = blockIdx.x & 15;
    int d0 = dt * 64, e0 = es * 64;
    int t = threadIdx.x;
    #pragma unroll
    for (int k = 0; k < 16; k++) {
        int idx = t + k * 256;
        int r = idx >> 6, c = idx & 63;
        Ws[r * 65 + c] = W[(size_t)(d0 + r) * Dn + e0 + c];
    }
    #pragma unroll
    for (int k = 0; k < 8; k++) {
        int idx = t + k * 256;
        int b = idx >> 6, c = idx & 63;
        Ys[b * 64 + c] = g_ys[b * Dn + e0 + c];
    }
    __syncthreads();
    int bg = t >> 5, dg = t & 31;
    float a00=0,a01=0,a10=0,a11=0,a20=0,a21=0,a30=0,a31=0;
    #pragma unroll 8
    for (int c = 0; c < 64; c++) {
        float w0 = Ws[dg * 65 + c];
        float w1 = Ws[(dg + 32) * 65 + c];
        float y0 = Ys[(bg * 4 + 0) * 64 + c];
        float y1 = Ys[(bg * 4 + 1) * 64 + c];
        float y2 = Ys[(bg * 4 + 2) * 64 + c];
        float y3 = Ys[(bg * 4 + 3) * 64 + c];
        a00 += y0 * w0; a01 += y0 * w1;
        a10 += y1 * w0; a11 += y1 * w1;
        a20 += y2 * w0; a21 += y2 * w1;
        a30 += y3 * w0; a31 += y3 * w1;
    }
    atomicAdd(&g_u[(bg * 4 + 0) * Dn + d0 + dg],      a00);
    atomicAdd(&g_u[(bg * 4 + 0) * Dn + d0 + dg + 32], a01);
    atomicAdd(&g_u[(bg * 4 + 1) * Dn + d0 + dg],      a10);
    atomicAdd(&g_u[(bg * 4 + 1) * Dn + d0 + dg + 32], a11);
    atomicAdd(&g_u[(bg * 4 + 2) * Dn + d0 + dg],      a20);
    atomicAdd(&g_u[(bg * 4 + 2) * Dn + d0 + dg + 32], a21);
    atomicAdd(&g_u[(bg * 4 + 3) * Dn + d0 + dg],      a30);
    atomicAdd(&g_u[(bg * 4 + 3) * Dn + d0 + dg + 32], a31);
}

// ===================== K3: fused f + online softmax + partial zs ====================
// ROW-PARALLEL: block covers all 1024 cols of each row; warp w owns cols
// [128w,128w+128), lane owns one float4. Per-thread state: u(4)+acc(4)+r(16)
// regs -> no spill, 4-5 CTAs/SM. Rows processed in batches of 4.
__global__ __launch_bounds__(256, 4) void k3_main(
    const float* __restrict__ E, const void* __restrict__ maskp,
    float* __restrict__ fout)
{
    __shared__ float sPart[4][8];   // [row-in-batch][warp] partial dots
    __shared__ float sF[4];         // broadcast logits

    int t = threadIdx.x, w = t >> 5, lane = t & 31;
    int bx = blockIdx.x;
    int b = bx >> 5, chunk = bx & 31;
    int mode = g_mode;

    // thread-resident u slice (its own 4 columns), scaled by 1/S (folds mean)
    float4 u;
    {
        const float invS = 1.0f / 2048.0f;
        u = reinterpret_cast<const float4*>(g_u + b * Dn)[t];
        u.x *= invS; u.y *= invS; u.z *= invS; u.w *= invS;
    }

    float4 acc = make_float4(0.f, 0.f, 0.f, 0.f);
    float m = -1.0e30f, Z = 0.f;

    int s0 = chunk * RPS;
    const float4* Ebase = reinterpret_cast<const float4*>(E)
                        + (size_t)(b * Sn + s0) * 256 + t;   // t == w*32+lane

    #pragma unroll 1
    for (int batch = 0; batch < RPS / 4; batch++) {
        // front-batched loads: 4 rows, this thread's float4 column
        float4 r0 = Ebase[(size_t)(batch * 4 + 0) * 256];
        float4 r1 = Ebase[(size_t)(batch * 4 + 1) * 256];
        float4 r2 = Ebase[(size_t)(batch * 4 + 2) * 256];
        float4 r3 = Ebase[(size_t)(batch * 4 + 3) * 256];

        // warp-partial dots over this warp's 128 columns
        float d0 = r0.x*u.x + r0.y*u.y + r0.z*u.z + r0.w*u.w;
        float d1 = r1.x*u.x + r1.y*u.y + r1.z*u.z + r1.w*u.w;
        float d2 = r2.x*u.x + r2.y*u.y + r2.z*u.z + r2.w*u.w;
        float d3 = r3.x*u.x + r3.y*u.y + r3.z*u.z + r3.w*u.w;
        #pragma unroll
        for (int o = 16; o; o >>= 1) {
            d0 += __shfl_xor_sync(0xffffffffu, d0, o);
            d1 += __shfl_xor_sync(0xffffffffu, d1, o);
            d2 += __shfl_xor_sync(0xffffffffu, d2, o);
            d3 += __shfl_xor_sync(0xffffffffu, d3, o);
        }
        if (lane == 0) {
            sPart[0][w] = d0; sPart[1][w] = d1;
            sPart[2][w] = d2; sPart[3][w] = d3;
        }
        __syncthreads();

        // warp 0 finishes the 4 rows: lane groups of 8 reduce one row each
        if (w == 0) {
            int i = lane >> 3, j = lane & 7;
            float v = sPart[i][j];
            v += __shfl_xor_sync(0xffffffffu, v, 4);
            v += __shfl_xor_sync(0xffffffffu, v, 2);
            v += __shfl_xor_sync(0xffffffffu, v, 1);
            if (j == 0) {
                int s = s0 + batch * 4 + i;
                int midx = b * Sn + s;
                bool mk;
                if (mode == 1)      mk = ((const int*)maskp)[midx] != 0;
                else if (mode == 2) mk = ((const float*)maskp)[midx] != 0.f;
                else                mk = ((const unsigned char*)maskp)[midx] != 0;
                float f = mk ? v : -1.0e9f;
                fout[midx] = f;          // raw logit; K4 normalizes
                sF[i] = f;
            }
        }
        __syncthreads();

        // all threads update block-uniform softmax state + their acc columns
        float f0 = sF[0], f1 = sF[1], f2 = sF[2], f3 = sF[3];
        float fm = fmaxf(fmaxf(f0, f1), fmaxf(f2, f3));
        if (fm > m) {                    // block-uniform branch, rare
            float sc = __expf(m - fm);
            acc.x *= sc; acc.y *= sc; acc.z *= sc; acc.w *= sc;
            Z *= sc;
            m = fm;
        }
        float p0 = __expf(f0 - m), p1 = __expf(f1 - m);
        float p2 = __expf(f2 - m), p3 = __expf(f3 - m);
        Z += (p0 + p1) + (p2 + p3);
        acc.x += p0*r0.x + p1*r1.x + p2*r2.x + p3*r3.x;
        acc.y += p0*r0.y + p1*r1.y + p2*r2.y + p3*r3.y;
        acc.z += p0*r0.z + p1*r1.z + p2*r2.z + p3*r3.z;
        acc.w += p0*r0.w + p1*r1.w + p2*r2.w + p3*r3.w;
    }

    // direct store: 256 threads tile the 1024 cols exactly once
    reinterpret_cast<float4*>(g_acc)[(size_t)bx * 256 + t] = acc;
    if (t == 0) { g_m[bx] = m; g_Z[bx] = Z; }
}

// ===================== K4: merge 32 chunks, write zs, normalize f ==================
// grid 256 = (b:32) x (part:8); 256 threads.
__global__ __launch_bounds__(256) void k4_final(float* __restrict__ out) {
    int bx = blockIdx.x;
    int b = bx >> 3, j = bx & 7;
    int t = threadIdx.x;

    float M = -1.0e30f;
    #pragma unroll
    for (int c = 0; c < K1S; c++) M = fmaxf(M, g_m[b * K1S + c]);
    float sc[K1S];
    float Z = 0.f;
    #pragma unroll
    for (int c = 0; c < K1S; c++) {
        sc[c] = __expf(g_m[b * K1S + c] - M);
        Z += g_Z[b * K1S + c] * sc[c];
    }
    float rinv = 1.0f / Z;

    if (t < 128) {
        int col = j * 128 + t;
        float s = 0.f;
        #pragma unroll
        for (int c = 0; c < K1S; c++)
            s += sc[c] * g_acc[((size_t)(b * K1S + c) << 10) + col];
        out[b * Dn + col] = s * rinv;
    }

    float* f = out + Bn * Dn;
    int idx = b * Sn + j * 256 + t;
    f[idx] = __expf(f[idx] - M) * rinv;
}

extern "C" void kernel_launch(void* const* d_in, const int* in_sizes, int n_in,
                              void* d_out, int out_size) {
    const float* E    = (const float*)d_in[0];
    const void*  mask = d_in[1];
    const float* W    = (const float*)d_in[2];
    float* out = (float*)d_out;

    k1_colsum<<<1024, 256>>>(E, (const unsigned int*)mask);
    k1_reduce<<<32, 256>>>();
    k2_u     <<<256, 256>>>(W);
    k3_main  <<<1024, 256>>>(E, mask, out + Bn * Dn);
    k4_final <<<256, 256>>>(out);
}

// round 16
// speedup vs baseline: 1.0378x; 1.0322x over previous
#include <cuda_runtime.h>

#define Bn 32
#define Sn 2048
#define Dn 1024
#define K1S 32          // S-splits in K1 / chunks in K3 (64 rows each)
#define RPS 64          // rows per split/chunk

// ---- scratch (device globals; no allocations allowed) ----
__device__ float g_ysp[K1S * Bn * Dn];   // [split][b][d] partial column sums (4 MB)
__device__ float g_ys[Bn * Dn];          // column sums of E over S
__device__ float g_u[Bn * Dn];           // u[b,d] = sum_e W[d,e]*ys_sum[b,e]
__device__ float g_acc[Bn * K1S * Dn];   // per-(b,chunk) partial zs (4 MB)
__device__ float g_m[Bn * K1S];          // per-(b,chunk) softmax max
__device__ float g_Z[Bn * K1S];          // per-(b,chunk) softmax denom (at g_m)
__device__ int   g_mode;                 // mask dtype: 0=u8 1=i32 2=f32

// ===================== K1: partial column sums of E =====================
// grid 1024 = (b:32) x (split:32); 256 threads, thread t owns float4 col t.
__global__ __launch_bounds__(256) void k1_colsum(const float* __restrict__ E,
                                                 const unsigned int* __restrict__ maskw) {
    int bx = blockIdx.x;
    int b  = bx >> 5;
    int sh = bx & 31;
    int t  = threadIdx.x;

    if (bx == 0 && t == 0) {
        bool allLe1 = true, allF = true;
        #pragma unroll 4
        for (int i = 0; i < 64; i++) {
            unsigned int v = maskw[i];
            if (v > 1u) allLe1 = false;
            if (v != 0u && v != 0x3F800000u) allF = false;
        }
        g_mode = allLe1 ? 1 : (allF ? 2 : 0);
    }

    const float4* p = reinterpret_cast<const float4*>(E)
                    + (size_t)(b * Sn + sh * RPS) * 256 + t;
    float4 a0 = make_float4(0.f,0.f,0.f,0.f), a1 = a0, a2 = a0, a3 = a0;
    #pragma unroll 4
    for (int s = 0; s < RPS; s += 4) {
        float4 v0 = p[(size_t)(s + 0) * 256];
        float4 v1 = p[(size_t)(s + 1) * 256];
        float4 v2 = p[(size_t)(s + 2) * 256];
        float4 v3 = p[(size_t)(s + 3) * 256];
        a0.x += v0.x; a0.y += v0.y; a0.z += v0.z; a0.w += v0.w;
        a1.x += v1.x; a1.y += v1.y; a1.z += v1.z; a1.w += v1.w;
        a2.x += v2.x; a2.y += v2.y; a2.z += v2.z; a2.w += v2.w;
        a3.x += v3.x; a3.y += v3.y; a3.z += v3.z; a3.w += v3.w;
    }
    float4 s4 = make_float4((a0.x + a1.x) + (a2.x + a3.x),
                            (a0.y + a1.y) + (a2.y + a3.y),
                            (a0.z + a1.z) + (a2.z + a3.z),
                            (a0.w + a1.w) + (a2.w + a3.w));
    reinterpret_cast<float4*>(g_ysp)[(size_t)(sh * Bn + b) * 256 + t] = s4;
}

// ===================== K1r: reduce 32 slices -> g_ys; zero g_u ==============
__global__ __launch_bounds__(256) void k1_reduce() {
    int b = blockIdx.x, t = threadIdx.x;
    const float4* base = reinterpret_cast<const float4*>(g_ysp);
    float4 s = make_float4(0.f, 0.f, 0.f, 0.f);
    #pragma unroll
    for (int c = 0; c < K1S; c++) {
        float4 v = base[(size_t)(c * Bn + b) * 256 + t];
        s.x += v.x; s.y += v.y; s.z += v.z; s.w += v.w;
    }
    reinterpret_cast<float4*>(g_ys)[b * 256 + t] = s;
    reinterpret_cast<float4*>(g_u)[b * 256 + t] = make_float4(0.f, 0.f, 0.f, 0.f);
}

// ===================== K2: u[b,d] = sum_e W[d,e] * ys_sum[b,e] =====================
__global__ __launch_bounds__(256) void k2_u(const float* __restrict__ W) {
    __shared__ float Ws[64 * 65];
    __shared__ float Ys[32 * 64];
    int dt = blockIdx.x >> 4, es = blockIdx.x & 15;
    int d0 = dt * 64, e0 = es * 64;
    int t = threadIdx.x;
    #pragma unroll
    for (int k = 0; k < 16; k++) {
        int idx = t + k * 256;
        int r = idx >> 6, c = idx & 63;
        Ws[r * 65 + c] = W[(size_t)(d0 + r) * Dn + e0 + c];
    }
    #pragma unroll
    for (int k = 0; k < 8; k++) {
        int idx = t + k * 256;
        int b = idx >> 6, c = idx & 63;
        Ys[b * 64 + c] = g_ys[b * Dn + e0 + c];
    }
    __syncthreads();
    int bg = t >> 5, dg = t & 31;
    float a00=0,a01=0,a10=0,a11=0,a20=0,a21=0,a30=0,a31=0;
    #pragma unroll 8
    for (int c = 0; c < 64; c++) {
        float w0 = Ws[dg * 65 + c];
        float w1 = Ws[(dg + 32) * 65 + c];
        float y0 = Ys[(bg * 4 + 0) * 64 + c];
        float y1 = Ys[(bg * 4 + 1) * 64 + c];
        float y2 = Ys[(bg * 4 + 2) * 64 + c];
        float y3 = Ys[(bg * 4 + 3) * 64 + c];
        a00 += y0 * w0; a01 += y0 * w1;
        a10 += y1 * w0; a11 += y1 * w1;
        a20 += y2 * w0; a21 += y2 * w1;
        a30 += y3 * w0; a31 += y3 * w1;
    }
    atomicAdd(&g_u[(bg * 4 + 0) * Dn + d0 + dg],      a00);
    atomicAdd(&g_u[(bg * 4 + 0) * Dn + d0 + dg + 32], a01);
    atomicAdd(&g_u[(bg * 4 + 1) * Dn + d0 + dg],      a10);
    atomicAdd(&g_u[(bg * 4 + 1) * Dn + d0 + dg + 32], a11);
    atomicAdd(&g_u[(bg * 4 + 2) * Dn + d0 + dg],      a20);
    atomicAdd(&g_u[(bg * 4 + 2) * Dn + d0 + dg + 32], a21);
    atomicAdd(&g_u[(bg * 4 + 3) * Dn + d0 + dg],      a30);
    atomicAdd(&g_u[(bg * 4 + 3) * Dn + d0 + dg + 32], a31);
}

// ===================== K3: fused f + online softmax + partial zs ====================
// Row-parallel, ONE barrier per 4-row batch, no serial warp0 phase.
// Warp dot-reduce: 2-level pack-fold (9 shfls for 4 rows); results land in
// lane-quarters with row order {0,2,1,3} (tracked through smem slots).
__global__ __launch_bounds__(256, 4) void k3_main(
    const float* __restrict__ E, const void* __restrict__ maskp,
    float* __restrict__ fout)
{
    __shared__ float sPart[2][32];    // [parity][slot(4) * warp(8)] partial dots

    int t = threadIdx.x, w = t >> 5, lane = t & 31;
    int bx = blockIdx.x;
    int b = bx >> 5, chunk = bx & 31;
    int mode = g_mode;

    float4 u;
    {
        const float invS = 1.0f / 2048.0f;
        u = reinterpret_cast<const float4*>(g_u + b * Dn)[t];
        u.x *= invS; u.y *= invS; u.z *= invS; u.w *= invS;
    }

    float4 acc = make_float4(0.f, 0.f, 0.f, 0.f);
    float m = -1.0e30f, Z = 0.f;

    int s0 = chunk * RPS;
    const float4* Ebase = reinterpret_cast<const float4*>(E)
                        + (size_t)(b * Sn + s0) * 256 + t;
    bool hi16 = (lane & 16);
    bool hi8  = (lane & 8);

    #pragma unroll 2
    for (int batch = 0; batch < RPS / 4; batch++) {
        int p = batch & 1;
        // front-batched loads: 4 rows, this thread's float4 column
        float4 r0 = Ebase[(size_t)(batch * 4 + 0) * 256];
        float4 r1 = Ebase[(size_t)(batch * 4 + 1) * 256];
        float4 r2 = Ebase[(size_t)(batch * 4 + 2) * 256];
        float4 r3 = Ebase[(size_t)(batch * 4 + 3) * 256];

        float d0 = r0.x*u.x + r0.y*u.y + r0.z*u.z + r0.w*u.w;
        float d1 = r1.x*u.x + r1.y*u.y + r1.z*u.z + r1.w*u.w;
        float d2 = r2.x*u.x + r2.y*u.y + r2.z*u.z + r2.w*u.w;
        float d3 = r3.x*u.x + r3.y*u.y + r3.z*u.z + r3.w*u.w;

        // level 1 (fold 16): lanes<16 -> row0/row2 partials, lanes>=16 -> row1/row3
        float x01 = hi16 ? d1 : d0;
        float o01 = hi16 ? d0 : d1;
        x01 += __shfl_xor_sync(0xffffffffu, o01, 16);
        float x23 = hi16 ? d3 : d2;
        float o23 = hi16 ? d2 : d3;
        x23 += __shfl_xor_sync(0xffffffffu, o23, 16);
        // level 2 (fold 8): quarters hold rows {0,2,1,3}
        float y = hi8 ? x23 : x01;
        float o = hi8 ? x01 : x23;
        y += __shfl_xor_sync(0xffffffffu, o, 8);
        // finish within 8-lane groups
        y += __shfl_xor_sync(0xffffffffu, y, 4);
        y += __shfl_xor_sync(0xffffffffu, y, 2);
        y += __shfl_xor_sync(0xffffffffu, y, 1);
        // slot layout: slot q of warp w holds row perm(q), perm={0,2,1,3}
        if ((lane & 7) == 0) sPart[p][(lane >> 3) * 8 + w] = y;
        __syncthreads();

        // every thread: coalesced 1-float LDS, 3-shfl cross-warp reduce, broadcast
        float v = sPart[p][lane];
        v += __shfl_xor_sync(0xffffffffu, v, 4);
        v += __shfl_xor_sync(0xffffffffu, v, 2);
        v += __shfl_xor_sync(0xffffffffu, v, 1);
        float f0 = __shfl_sync(0xffffffffu, v, 0);    // slot0 = row0
        float f2 = __shfl_sync(0xffffffffu, v, 8);    // slot1 = row2
        float f1 = __shfl_sync(0xffffffffu, v, 16);   // slot2 = row1
        float f3 = __shfl_sync(0xffffffffu, v, 24);   // slot3 = row3

        // mask (broadcast loads; all threads same addresses)
        int midx = b * Sn + s0 + batch * 4;
        bool mk0, mk1, mk2, mk3;
        if (mode == 1) {
            const int* mp = (const int*)maskp + midx;
            mk0 = mp[0] != 0; mk1 = mp[1] != 0; mk2 = mp[2] != 0; mk3 = mp[3] != 0;
        } else if (mode == 2) {
            const float* mp = (const float*)maskp + midx;
            mk0 = mp[0] != 0.f; mk1 = mp[1] != 0.f; mk2 = mp[2] != 0.f; mk3 = mp[3] != 0.f;
        } else {
            const unsigned char* mp = (const unsigned char*)maskp + midx;
            mk0 = mp[0] != 0; mk1 = mp[1] != 0; mk2 = mp[2] != 0; mk3 = mp[3] != 0;
        }
        f0 = mk0 ? f0 : -1.0e9f;
        f1 = mk1 ? f1 : -1.0e9f;
        f2 = mk2 ? f2 : -1.0e9f;
        f3 = mk3 ? f3 : -1.0e9f;
        if (t == 0) {
            fout[midx + 0] = f0; fout[midx + 1] = f1;
            fout[midx + 2] = f2; fout[midx + 3] = f3;
        }

        float fm = fmaxf(fmaxf(f0, f1), fmaxf(f2, f3));
        if (fm > m) {                    // block-uniform branch, rare
            float sc = __expf(m - fm);
            acc.x *= sc; acc.y *= sc; acc.z *= sc; acc.w *= sc;
            Z *= sc;
            m = fm;
        }
        float p0 = __expf(f0 - m), p1 = __expf(f1 - m);
        float p2 = __expf(f2 - m), p3 = __expf(f3 - m);
        Z += (p0 + p1) + (p2 + p3);
        acc.x += p0*r0.x + p1*r1.x + p2*r2.x + p3*r3.x;
        acc.y += p0*r0.y + p1*r1.y + p2*r2.y + p3*r3.y;
        acc.z += p0*r0.z + p1*r1.z + p2*r2.z + p3*r3.z;
        acc.w += p0*r0.w + p1*r1.w + p2*r2.w + p3*r3.w;
    }

    reinterpret_cast<float4*>(g_acc)[(size_t)bx * 256 + t] = acc;
    if (t == 0) { g_m[bx] = m; g_Z[bx] = Z; }
}

// ===================== K4: merge 32 chunks, write zs, normalize f ==================
__global__ __launch_bounds__(256) void k4_final(float* __restrict__ out) {
    int bx = blockIdx.x;
    int b = bx >> 3, j = bx & 7;
    int t = threadIdx.x;

    float M = -1.0e30f;
    #pragma unroll
    for (int c = 0; c < K1S; c++) M = fmaxf(M, g_m[b * K1S + c]);
    float sc[K1S];
    float Z = 0.f;
    #pragma unroll
    for (int c = 0; c < K1S; c++) {
        sc[c] = __expf(g_m[b * K1S + c] - M);
        Z += g_Z[b * K1S + c] * sc[c];
    }
    float rinv = 1.0f / Z;

    if (t < 128) {
        int col = j * 128 + t;
        float s = 0.f;
        #pragma unroll
        for (int c = 0; c < K1S; c++)
            s += sc[c] * g_acc[((size_t)(b * K1S + c) << 10) + col];
        out[b * Dn + col] = s * rinv;
    }

    float* f = out + Bn * Dn;
    int idx = b * Sn + j * 256 + t;
    f[idx] = __expf(f[idx] - M) * rinv;
}

extern "C" void kernel_launch(void* const* d_in, const int* in_sizes, int n_in,
                              void* d_out, int out_size) {
    const float* E    = (const float*)d_in[0];
    const void*  mask = d_in[1];
    const float* W    = (const float*)d_in[2];
    float* out = (float*)d_out;

    k1_colsum<<<1024, 256>>>(E, (const unsigned int*)mask);
    k1_reduce<<<32, 256>>>();
    k2_u     <<<256, 256>>>(W);
    k3_main  <<<1024, 256>>>(E, mask, out + Bn * Dn);
    k4_final <<<256, 256>>>(out);
}